// round 1
// baseline (speedup 1.0000x reference)
#include <cuda_runtime.h>

// RNN_13855564496941: Euler-integrated RNN, T=1024 steps, B=4096, H=50.
// Batch columns are independent -> persistent per-CTA time loop, no grid sync.
// CTA = 32 columns x 13 row-chunks of 4 rows (H padded 50->52), 416 threads.
// dt*Jrec^T cached in SMEM; per step: act = 1+tanh(h) -> SMEM, sync, 50-j
// matvec (broadcast LDS.128 of 4 Jrec rows + 1 act LDS.32 per j), sync,
// warp 0 reduces the Jout partials and streams out[t,:].

namespace {
constexpr int T_STEPS = 1024;
constexpr int B_DIM   = 4096;
constexpr int H_DIM   = 50;
constexpr int H_PAD   = 52;   // pad so 4-row chunks tile evenly & float4 aligned
constexpr int NC      = 32;   // batch columns per CTA
constexpr int SCH     = 13;   // row chunks (13 * 4 = 52)
constexpr int RR      = 4;    // rows per thread
constexpr int NTHR    = NC * SCH;  // 416 threads = 13 full warps
constexpr float DT    = 0.1f;
constexpr float ONE_MINUS_DT = 0.9f;
}

__device__ __forceinline__ float one_plus_tanh(float x) {
    // 1 + tanh(x) = 2*e^{2x} / (e^{2x} + 1); clamp avoids inf/inf for huge x.
    float e = __expf(2.0f * fminf(x, 30.0f));
    return __fdividef(2.0f * e, e + 1.0f);
}

__global__ __launch_bounds__(NTHR, 1) void rnn_persist(
    const float* __restrict__ inpt,   // (T, B)
    const float* __restrict__ Jin,    // (H, 1)
    const float* __restrict__ Jrec,   // (H, H)
    const float* __restrict__ Jout,   // (1, H)
    const float* __restrict__ bias,   // (H, 1)
    const float* __restrict__ h0,     // (H, B)
    float* __restrict__ out)          // (T, B)
{
    __shared__ float sW[H_DIM][H_PAD];   // sW[j][i] = dt * Jrec[i][j] (transposed, scaled)
    __shared__ float sAct[H_PAD][NC];    // act[j][col]; rows 50..51 written, never read
    __shared__ float sPart[SCH][NC];     // Jout partial dots per row-chunk
    __shared__ float sVec[3][H_PAD];     // 0: dt*Jin, 1: dt*bias, 2: Jout

    const int tid  = threadIdx.x;
    const int col  = tid & (NC - 1);     // lane within warp (NC == 32)
    const int s    = tid >> 5;           // warp index == row chunk
    const int r0   = s * RR;
    const int gcol = blockIdx.x * NC + col;

    // ---- one-time init: stage weights into SMEM ----
    for (int idx = tid; idx < H_DIM * H_PAD; idx += NTHR) {
        int j = idx / H_PAD;
        int i = idx - j * H_PAD;
        sW[j][i] = (i < H_DIM) ? DT * Jrec[i * H_DIM + j] : 0.0f;
    }
    if (tid < H_PAD) {
        bool v = tid < H_DIM;
        sVec[0][tid] = v ? DT * Jin[tid]  : 0.0f;
        sVec[1][tid] = v ? DT * bias[tid] : 0.0f;
        sVec[2][tid] = v ? Jout[tid]      : 0.0f;
    }
    __syncthreads();

    float h[RR], jin[RR], bs[RR], jo[RR];
    #pragma unroll
    for (int k = 0; k < RR; k++) {
        int r = r0 + k;
        h[k]  = (r < H_DIM) ? h0[r * B_DIM + gcol] : 0.0f;  // dummy rows stay 0 forever
        jin[k] = sVec[0][r];
        bs[k]  = sVec[1][r];
        jo[k]  = sVec[2][r];
    }

    const float* xptr = inpt + gcol;
    float*       optr = out + gcol;

    for (int t = 0; t < T_STEPS; t++) {
        // issue x load early; latency hidden behind tanh + barrier
        float x = *xptr;
        xptr += B_DIM;

        #pragma unroll
        for (int k = 0; k < RR; k++)
            sAct[r0 + k][col] = one_plus_tanh(h[k]);
        __syncthreads();

        float acc[RR];
        #pragma unroll
        for (int k = 0; k < RR; k++)
            acc[k] = fmaf(ONE_MINUS_DT, h[k], fmaf(jin[k], x, bs[k]));

        #pragma unroll
        for (int j = 0; j < H_DIM; j++) {
            float a = sAct[j][col];                                  // conflict-free
            const float4 w = *reinterpret_cast<const float4*>(&sW[j][r0]);  // warp broadcast
            acc[0] = fmaf(w.x, a, acc[0]);
            acc[1] = fmaf(w.y, a, acc[1]);
            acc[2] = fmaf(w.z, a, acc[2]);
            acc[3] = fmaf(w.w, a, acc[3]);
        }

        float p = 0.0f;
        #pragma unroll
        for (int k = 0; k < RR; k++) {
            h[k] = acc[k];
            p = fmaf(jo[k], acc[k], p);
        }
        sPart[s][col] = p;
        __syncthreads();
        // (sPart reads below are ordered before the next sPart writes by the
        //  __syncthreads() at the top of the next iteration.)

        if (s == 0) {
            float o = sPart[0][col];
            #pragma unroll
            for (int q = 1; q < SCH; q++) o += sPart[q][col];
            *optr = o;   // coalesced 128B per CTA
        }
        optr += B_DIM;
    }
}

extern "C" void kernel_launch(void* const* d_in, const int* in_sizes, int n_in,
                              void* d_out, int out_size) {
    const float* inpt = (const float*)d_in[0];
    const float* Jin  = (const float*)d_in[1];
    const float* Jrec = (const float*)d_in[2];
    const float* Jout = (const float*)d_in[3];
    const float* bias = (const float*)d_in[4];
    const float* h0   = (const float*)d_in[5];
    float* out = (float*)d_out;

    rnn_persist<<<B_DIM / NC, NTHR>>>(inpt, Jin, Jrec, Jout, bias, h0, out);
}

// round 2
// speedup vs baseline: 1.0485x; 1.0485x over previous
#include <cuda_runtime.h>

// RNN_13855564496941: Euler RNN, T=1024, B=4096, H=50.
// R2: 256 CTAs x 16 cols (208 thr, rows padded 50->52, 4 rows/thread).
//     ~2 CTAs/SM -> barrier overlap; ONE __syncthreads per step via
//     double-buffered sAct/sPart and pipelined (one-step-delayed) output.

namespace {
constexpr int T_STEPS = 1024;
constexpr int B_DIM   = 4096;
constexpr int H_DIM   = 50;
constexpr int H_PAD   = 52;     // 13 chunks of 4 rows
constexpr int NC      = 16;     // batch columns per CTA
constexpr int SCH     = 13;     // row chunks
constexpr int RR      = 4;      // rows per thread
constexpr int NTHR    = NC * SCH;   // 208 threads
constexpr int GRID    = B_DIM / NC; // 256 CTAs
constexpr float DT    = 0.1f;
constexpr float ONE_MINUS_DT = 0.9f;
}

__device__ __forceinline__ float one_plus_tanh(float x) {
    // 1 + tanh(x) = 2 e^{2x} / (e^{2x} + 1)
    float e = __expf(2.0f * fminf(x, 30.0f));
    return __fdividef(2.0f * e, e + 1.0f);
}

__global__ __launch_bounds__(NTHR, 2) void rnn_persist(
    const float* __restrict__ inpt,   // (T, B)
    const float* __restrict__ Jin,    // (H, 1)
    const float* __restrict__ Jrec,   // (H, H)
    const float* __restrict__ Jout,   // (1, H)
    const float* __restrict__ bias,   // (H, 1)
    const float* __restrict__ h0,     // (H, B)
    float* __restrict__ out)          // (T, B)
{
    __shared__ float sW[H_DIM][H_PAD];      // sW[j][i] = dt * Jrec[i][j]
    __shared__ float sAct[2][H_PAD][NC];    // double-buffered activations
    __shared__ float sPart[2][SCH][NC];     // double-buffered Jout partials
    __shared__ float sVec[3][H_PAD];        // dt*Jin, dt*bias, Jout

    const int tid   = threadIdx.x;
    const int col   = tid & (NC - 1);
    const int chunk = tid >> 4;             // 0..12
    const int r0    = chunk * RR;
    const int gcol  = blockIdx.x * NC + col;

    // ---- one-time init ----
    for (int idx = tid; idx < H_DIM * H_PAD; idx += NTHR) {
        int j = idx / H_PAD;
        int i = idx - j * H_PAD;
        sW[j][i] = (i < H_DIM) ? DT * Jrec[i * H_DIM + j] : 0.0f;
    }
    if (tid < H_PAD) {
        bool v = tid < H_DIM;
        sVec[0][tid] = v ? DT * Jin[tid]  : 0.0f;
        sVec[1][tid] = v ? DT * bias[tid] : 0.0f;
        sVec[2][tid] = v ? Jout[tid]      : 0.0f;
    }
    __syncthreads();

    float h[RR], jin[RR], bs[RR], jo[RR];
    #pragma unroll
    for (int k = 0; k < RR; k++) {
        int r = r0 + k;
        h[k]  = (r < H_DIM) ? h0[r * B_DIM + gcol] : 0.0f;
        jin[k] = sVec[0][r];
        bs[k]  = sVec[1][r];
        jo[k]  = sVec[2][r];
    }

    const float* xptr = inpt + gcol;
    float*       optr = out + gcol;        // advanced with t; writes lag by 1

    float x = *xptr;                        // prefetch x_0
    int p = 0;

    for (int t = 0; t < T_STEPS; t++) {
        // prefetch x_{t+1}; the load spans the whole matvec below
        float xNext = 0.0f;
        if (t + 1 < T_STEPS) xNext = xptr[B_DIM];
        xptr += B_DIM;

        #pragma unroll
        for (int k = 0; k < RR; k++)
            sAct[p][r0 + k][col] = one_plus_tanh(h[k]);

        __syncthreads();   // the ONLY barrier per step

        // pipelined output: step t-1 partials are complete and fenced now
        if (chunk == 0 && t > 0) {
            float o = sPart[p ^ 1][0][col];
            #pragma unroll
            for (int q = 1; q < SCH; q++) o += sPart[p ^ 1][q][col];
            *optr = o;
            optr += B_DIM;
        }

        float acc[RR];
        #pragma unroll
        for (int k = 0; k < RR; k++)
            acc[k] = fmaf(ONE_MINUS_DT, h[k], fmaf(jin[k], x, bs[k]));

        #pragma unroll
        for (int j = 0; j < H_DIM; j++) {
            float a = sAct[p][j][col];                                    // 1 wf
            const float4 w = *reinterpret_cast<const float4*>(&sW[j][r0]); // bcast
            acc[0] = fmaf(w.x, a, acc[0]);
            acc[1] = fmaf(w.y, a, acc[1]);
            acc[2] = fmaf(w.z, a, acc[2]);
            acc[3] = fmaf(w.w, a, acc[3]);
        }

        float pt = 0.0f;
        #pragma unroll
        for (int k = 0; k < RR; k++) {
            h[k] = acc[k];
            pt = fmaf(jo[k], acc[k], pt);
        }
        sPart[p][chunk][col] = pt;

        x = xNext;
        p ^= 1;
    }

    // flush the last output (partials for step T-1 live in sPart[p^1])
    __syncthreads();
    if (chunk == 0) {
        float o = sPart[p ^ 1][0][col];
        #pragma unroll
        for (int q = 1; q < SCH; q++) o += sPart[p ^ 1][q][col];
        *optr = o;
    }
}

extern "C" void kernel_launch(void* const* d_in, const int* in_sizes, int n_in,
                              void* d_out, int out_size) {
    const float* inpt = (const float*)d_in[0];
    const float* Jin  = (const float*)d_in[1];
    const float* Jrec = (const float*)d_in[2];
    const float* Jout = (const float*)d_in[3];
    const float* bias = (const float*)d_in[4];
    const float* h0   = (const float*)d_in[5];
    float* out = (float*)d_out;

    rnn_persist<<<GRID, NTHR>>>(inpt, Jin, Jrec, Jout, bias, h0, out);
}